// round 4
// baseline (speedup 1.0000x reference)
#include <cuda_runtime.h>
#include <math.h>

#define IN_SIZE 448
#define OUT_SIZE 224
#define NBATCH 64
#define COLS_PER_THREAD 4
#define ROWS_PER_BLOCK 4

// Scratch (allocation-free per harness rules): per-batch sigmoid-mask tables + crop boxes.
__device__ float g_mrow[NBATCH][IN_SIZE];
__device__ float g_mcol[NBATCH][IN_SIZE];
__device__ float4 g_box[NBATCH];   // (w_off, w_end, h_off, h_end)

__device__ __forceinline__ float sig10(float z) {
    // sigmoid(10*z); expf saturates to inf -> 1/inf = 0 for very negative z (matches jax).
    return 1.0f / (1.0f + expf(-10.0f * z));
}

__global__ void racnn_prep_kernel(const float* __restrict__ locs) {
    int b = blockIdx.x;
    int t = threadIdx.x;  // 0..447

    float tx = locs[b * 3 + 0];
    float ty = locs[b * 3 + 1];
    float tl = locs[b * 3 + 2];

    // in_size == 448 path of the reference
    tl = fmaxf(tl, (float)IN_SIZE / 3.0f);
    tx = fminf(fmaxf(tx, tl), (float)IN_SIZE - tl);
    ty = fminf(fmaxf(ty, tl), (float)IN_SIZE - tl);

    float w_off = fmaxf(floorf(tx - tl), 0.0f);
    float h_off = fmaxf(floorf(ty - tl), 0.0f);
    float w_end = fminf(floorf(tx + tl), (float)IN_SIZE);
    float h_end = fminf(floorf(ty + tl), (float)IN_SIZE);

    float fi = (float)t;
    g_mrow[b][t] = sig10(fi - w_off) - sig10(fi - w_end);
    g_mcol[b][t] = sig10(fi - h_off) - sig10(fi - h_end);

    if (t == 0) g_box[b] = make_float4(w_off, w_end, h_off, h_end);
}

// Each thread: one output row, 4 consecutive output columns, all 3 channels.
// -> float4 coalesced stores, 48 independent gathers in flight per thread.
__global__ __launch_bounds__(224) void racnn_main_kernel(
    const float* __restrict__ img, float* __restrict__ out) {
    int jc0 = threadIdx.x * COLS_PER_THREAD;                    // 0,4,...,220
    int jr  = blockIdx.x * ROWS_PER_BLOCK + threadIdx.y;        // 0..223
    int b   = blockIdx.y;                                       // 0..63

    float4 box = g_box[b];
    float w_off = box.x, w_end = box.y, h_off = box.z, h_end = box.w;

    const float inv = 1.0f / (float)(OUT_SIZE - 1);
    float rscale = (w_end - w_off - 1.0f) * inv;
    float cscale = (h_end - h_off - 1.0f) * inv;

    // Row (shared by all 4 columns)
    float src_r = w_off + (float)jr * rscale;
    float r0f = fminf(fmaxf(floorf(src_r), 0.0f), (float)(IN_SIZE - 1));
    float wr = src_r - r0f;
    int r0 = (int)r0f;
    int r1 = min(r0 + 1, IN_SIZE - 1);
    float a0 = (1.0f - wr) * __ldg(&g_mrow[b][r0]);
    float a1 = wr          * __ldg(&g_mrow[b][r1]);

    // Columns
    int   c0[COLS_PER_THREAD], c1[COLS_PER_THREAD];
    float b0[COLS_PER_THREAD], b1[COLS_PER_THREAD];
    #pragma unroll
    for (int k = 0; k < COLS_PER_THREAD; k++) {
        float src_c = h_off + (float)(jc0 + k) * cscale;
        float c0f = fminf(fmaxf(floorf(src_c), 0.0f), (float)(IN_SIZE - 1));
        float wc = src_c - c0f;
        c0[k] = (int)c0f;
        c1[k] = min(c0[k] + 1, IN_SIZE - 1);
        b0[k] = (1.0f - wc) * __ldg(&g_mcol[b][c0[k]]);
        b1[k] = wc          * __ldg(&g_mcol[b][c1[k]]);
    }

    const float* base  = img + (size_t)b * 3 * IN_SIZE * IN_SIZE;
    float*       obase = out + (size_t)b * 3 * OUT_SIZE * OUT_SIZE
                             + (size_t)jr * OUT_SIZE + jc0;

    long ro0 = (long)r0 * IN_SIZE;
    long ro1 = (long)r1 * IN_SIZE;

    #pragma unroll
    for (int ch = 0; ch < 3; ch++) {
        const float* p = base + (size_t)ch * IN_SIZE * IN_SIZE;
        float4 res;
        float acc[COLS_PER_THREAD];
        #pragma unroll
        for (int k = 0; k < COLS_PER_THREAD; k++) {
            float p00 = __ldg(p + ro0 + c0[k]);
            float p01 = __ldg(p + ro0 + c1[k]);
            float p10 = __ldg(p + ro1 + c0[k]);
            float p11 = __ldg(p + ro1 + c1[k]);
            acc[k] = a0 * (b0[k] * p00 + b1[k] * p01)
                   + a1 * (b0[k] * p10 + b1[k] * p11);
        }
        res.x = acc[0]; res.y = acc[1]; res.z = acc[2]; res.w = acc[3];
        *reinterpret_cast<float4*>(obase + (size_t)ch * OUT_SIZE * OUT_SIZE) = res;
    }
}

extern "C" void kernel_launch(void* const* d_in, const int* in_sizes, int n_in,
                              void* d_out, int out_size) {
    const float* images = (const float*)d_in[0];  // [64, 3, 448, 448] f32
    const float* locs   = (const float*)d_in[1];  // [64, 3] f32
    float* out = (float*)d_out;                   // [64, 3, 224, 224] f32

    racnn_prep_kernel<<<NBATCH, IN_SIZE>>>(locs);

    dim3 block(OUT_SIZE / COLS_PER_THREAD, ROWS_PER_BLOCK);   // (56, 4) = 224 thr
    dim3 grid(OUT_SIZE / ROWS_PER_BLOCK, NBATCH);             // (56, 64)
    racnn_main_kernel<<<grid, block>>>(images, out);
}

// round 11
// speedup vs baseline: 1.2116x; 1.2116x over previous
#include <cuda_runtime.h>
#include <math.h>

#define IN_SIZE 448
#define OUT_SIZE 224
#define NBATCH 64
#define ROWS_PER_BLOCK 4

// Scratch (allocation-free per harness rules): per-batch sigmoid-mask tables + crop boxes.
__device__ float g_mrow[NBATCH][IN_SIZE];
__device__ float g_mcol[NBATCH][IN_SIZE];
__device__ float4 g_box[NBATCH];   // (w_off, w_end, h_off, h_end)

__device__ __forceinline__ float sig10(float z) {
    // sigmoid(10*z); expf saturates to inf -> 1/inf = 0 for very negative z (matches jax).
    return 1.0f / (1.0f + expf(-10.0f * z));
}

__global__ void racnn_prep_kernel(const float* __restrict__ locs) {
    int b = blockIdx.x;
    int t = threadIdx.x;  // 0..447

    float tx = locs[b * 3 + 0];
    float ty = locs[b * 3 + 1];
    float tl = locs[b * 3 + 2];

    // in_size == 448 path of the reference
    tl = fmaxf(tl, (float)IN_SIZE / 3.0f);
    tx = fminf(fmaxf(tx, tl), (float)IN_SIZE - tl);
    ty = fminf(fmaxf(ty, tl), (float)IN_SIZE - tl);

    float w_off = fmaxf(floorf(tx - tl), 0.0f);
    float h_off = fmaxf(floorf(ty - tl), 0.0f);
    float w_end = fminf(floorf(tx + tl), (float)IN_SIZE);
    float h_end = fminf(floorf(ty + tl), (float)IN_SIZE);

    float fi = (float)t;
    g_mrow[b][t] = sig10(fi - w_off) - sig10(fi - w_end);
    g_mcol[b][t] = sig10(fi - h_off) - sig10(fi - h_end);

    if (t == 0) g_box[b] = make_float4(w_off, w_end, h_off, h_end);
}

// One output column per thread (lanes adjacent in source space -> 2-3 L1 lines
// per gather instead of 6-7). Each thread covers 4 output rows x 3 channels.
__global__ __launch_bounds__(OUT_SIZE) void racnn_main_kernel(
    const float* __restrict__ img, float* __restrict__ out) {
    int jc      = threadIdx.x;                       // 0..223 (output column)
    int jr_base = blockIdx.x * ROWS_PER_BLOCK;       // 0,4,...,220
    int b       = blockIdx.y;                        // 0..63

    float4 box = g_box[b];
    float w_off = box.x, w_end = box.y, h_off = box.z, h_end = box.w;

    const float inv = 1.0f / (float)(OUT_SIZE - 1);
    float rscale = (w_end - w_off - 1.0f) * inv;
    float cscale = (h_end - h_off - 1.0f) * inv;

    // Column weights (once per thread, amortized over 12 outputs)
    float src_c = h_off + (float)jc * cscale;
    float c0f = fminf(fmaxf(floorf(src_c), 0.0f), (float)(IN_SIZE - 1));
    float wc = src_c - c0f;
    int c0 = (int)c0f;
    int c1 = min(c0 + 1, IN_SIZE - 1);
    float b0 = (1.0f - wc) * __ldg(&g_mcol[b][c0]);
    float b1 = wc          * __ldg(&g_mcol[b][c1]);

    // Row weights/offsets for the 4 rows this block covers
    float a0[ROWS_PER_BLOCK], a1[ROWS_PER_BLOCK];
    int   ro0[ROWS_PER_BLOCK], ro1[ROWS_PER_BLOCK];
    #pragma unroll
    for (int rr = 0; rr < ROWS_PER_BLOCK; rr++) {
        float src_r = w_off + (float)(jr_base + rr) * rscale;
        float r0f = fminf(fmaxf(floorf(src_r), 0.0f), (float)(IN_SIZE - 1));
        float wr = src_r - r0f;
        int r0 = (int)r0f;
        int r1 = min(r0 + 1, IN_SIZE - 1);
        a0[rr] = (1.0f - wr) * __ldg(&g_mrow[b][r0]);
        a1[rr] = wr          * __ldg(&g_mrow[b][r1]);
        ro0[rr] = r0 * IN_SIZE;
        ro1[rr] = r1 * IN_SIZE;
    }

    const float* base  = img + (size_t)b * 3 * IN_SIZE * IN_SIZE;
    float*       obase = out + (size_t)b * 3 * OUT_SIZE * OUT_SIZE
                             + (size_t)jr_base * OUT_SIZE + jc;

    #pragma unroll
    for (int ch = 0; ch < 3; ch++) {
        const float* p = base + (size_t)ch * IN_SIZE * IN_SIZE;

        // Batch all 16 gathers for this channel (MLP=16), then 4 stores.
        float p00[ROWS_PER_BLOCK], p01[ROWS_PER_BLOCK];
        float p10[ROWS_PER_BLOCK], p11[ROWS_PER_BLOCK];
        #pragma unroll
        for (int rr = 0; rr < ROWS_PER_BLOCK; rr++) {
            p00[rr] = __ldg(p + ro0[rr] + c0);
            p01[rr] = __ldg(p + ro0[rr] + c1);
            p10[rr] = __ldg(p + ro1[rr] + c0);
            p11[rr] = __ldg(p + ro1[rr] + c1);
        }

        float* o = obase + (size_t)ch * OUT_SIZE * OUT_SIZE;
        #pragma unroll
        for (int rr = 0; rr < ROWS_PER_BLOCK; rr++) {
            o[(size_t)rr * OUT_SIZE] =
                a0[rr] * (b0 * p00[rr] + b1 * p01[rr]) +
                a1[rr] * (b0 * p10[rr] + b1 * p11[rr]);
        }
    }
}

extern "C" void kernel_launch(void* const* d_in, const int* in_sizes, int n_in,
                              void* d_out, int out_size) {
    const float* images = (const float*)d_in[0];  // [64, 3, 448, 448] f32
    const float* locs   = (const float*)d_in[1];  // [64, 3] f32
    float* out = (float*)d_out;                   // [64, 3, 224, 224] f32

    racnn_prep_kernel<<<NBATCH, IN_SIZE>>>(locs);

    dim3 grid(OUT_SIZE / ROWS_PER_BLOCK, NBATCH);   // (56, 64)
    racnn_main_kernel<<<grid, OUT_SIZE>>>(images, out);
}